// round 3
// baseline (speedup 1.0000x reference)
#include <cuda_runtime.h>

#define T_DIM 32
#define C_DIM 512
#define H_DIM 56
#define W_DIM 56
#define EPSF  1e-6f

// Packed (lin, sq) pairs.
// Per-(t,h) reductions for the H axis (block-exclusive -> plain store)
__device__ float2 g_H[T_DIM * H_DIM];
// Per-(t,h,w) partials for the W axis, folded over h in the finish kernel
__device__ float2 g_pW[T_DIM * H_DIM * W_DIM];
// Final W-axis reductions
__device__ float2 g_W[T_DIM * W_DIM];

// ---------------------------------------------------------------------------
// Kernel 1: stream the whole tensor once. Block = one (t, h) pair.
// 224 threads = 14 float4-quads (w) x 16 row slots (c).
// ---------------------------------------------------------------------------
__global__ __launch_bounds__(224) void reduce_kernel(const float* __restrict__ x)
{
    const int h   = blockIdx.x;
    const int t   = blockIdx.y;
    const int tid = threadIdx.x;
    const int q   = tid % 14;   // which float4 within the 56-wide row
    const int r0  = tid / 14;   // row (channel) slot 0..15

    // base points at element (t, c=0, h, w=0); h*56 is a multiple of 4 -> 16B aligned
    const float4* __restrict__ base =
        (const float4*)(x + ((size_t)t * C_DIM * H_DIM + (size_t)h) * W_DIM);
    const int stride4 = (H_DIM * W_DIM) / 4;  // 784 float4 per channel

    float linh = 0.f, sqh = 0.f;
    float lw0 = 0.f, lw1 = 0.f, lw2 = 0.f, lw3 = 0.f;
    float sw0 = 0.f, sw1 = 0.f, sw2 = 0.f, sw3 = 0.f;

    #pragma unroll 4
    for (int c = r0; c < C_DIM; c += 16) {
        float4 v = base[(size_t)c * stride4 + q];
        linh += v.x + v.y + v.z + v.w;
        sqh  += v.x * v.x + v.y * v.y + v.z * v.z + v.w * v.w;
        lw0 += v.x;  sw0 += v.x * v.x;
        lw1 += v.y;  sw1 += v.y * v.y;
        lw2 += v.z;  sw2 += v.z * v.z;
        lw3 += v.w;  sw3 += v.w * v.w;
    }

    __shared__ float sbuf[224 * 8];  // reused for both reductions

    // ---- H reduction: shfl within warp, then thread 0 folds the 7 warps ----
    float a = linh, b = sqh;
    #pragma unroll
    for (int off = 16; off > 0; off >>= 1) {
        a += __shfl_down_sync(0xffffffffu, a, off);
        b += __shfl_down_sync(0xffffffffu, b, off);
    }
    const int wid  = tid >> 5;
    const int lane = tid & 31;
    if (lane == 0) { sbuf[wid] = a; sbuf[8 + wid] = b; }
    __syncthreads();
    if (tid == 0) {
        float la = 0.f, lb = 0.f;
        #pragma unroll
        for (int i = 0; i < 7; ++i) { la += sbuf[i]; lb += sbuf[8 + i]; }
        g_H[t * H_DIM + h] = make_float2(la, lb);
    }
    __syncthreads();  // done with sbuf for H

    // ---- W partials: each thread parks its 8 values, 56 threads gather ----
    float* my = &sbuf[tid * 8];
    my[0] = lw0; my[1] = lw1; my[2] = lw2; my[3] = lw3;
    my[4] = sw0; my[5] = sw1; my[6] = sw2; my[7] = sw3;
    __syncthreads();

    if (tid < W_DIM) {
        const int qq = tid >> 2;   // quad owning this w
        const int ii = tid & 3;    // element within quad
        float la = 0.f, lb = 0.f;
        #pragma unroll
        for (int r = 0; r < 16; ++r) {
            const float* src = &sbuf[(r * 14 + qq) * 8];
            la += src[ii];
            lb += src[4 + ii];
        }
        g_pW[(t * H_DIM + h) * W_DIM + tid] = make_float2(la, lb);
    }
}

// ---------------------------------------------------------------------------
// Kernel 2 (fused): fold W partials over h, then cumsums + sqrt + mean.
// One block of 1024 threads.
//   Phase A: 1792 (t,w) pairs reduced over 56 h values (L2-hot, float2 loads).
//   Phase B: 64 threads (32 t x 2 axes) do the length-56 scans.
//   Phase C: tree-reduce 64 partials to the scalar.
// ---------------------------------------------------------------------------
__global__ __launch_bounds__(1024) void finish_kernel(float* __restrict__ out)
{
    const int tid = threadIdx.x;

    // ---- Phase A: column-reduce W partials over h ----
    for (int p = tid; p < T_DIM * W_DIM; p += 1024) {
        const int t = p / W_DIM;
        const int w = p % W_DIM;
        float a = 0.f, b = 0.f;
        #pragma unroll 8
        for (int hh = 0; hh < H_DIM; ++hh) {
            float2 v = g_pW[(t * H_DIM + hh) * W_DIM + w];
            a += v.x;
            b += v.y;
        }
        g_W[t * W_DIM + w] = make_float2(a, b);
    }
    __syncthreads();

    // ---- Phase B: scans ----
    __shared__ float sh[64];
    if (tid < 64) {
        const int t  = tid & 31;
        const int ax = tid >> 5;  // 0 = H, 1 = W

        const float2* __restrict__ s = (ax ? g_W : g_H) + t * 56;

        const float n_other = (float)(C_DIM) * 56.f;  // 28672
        float total = 0.f;

        // suffix slices [i:]
        float csq = 0.f, clin = 0.f;
        #pragma unroll
        for (int i = 55; i >= 0; --i) {
            float2 v = s[i];
            clin += v.x;
            csq  += v.y;
            float n = n_other * (float)(56 - i);
            total += sqrtf(csq + 2.f * EPSF * clin + (EPSF * EPSF) * n) + EPSF;
        }
        // prefix slices [:j+1]
        csq = 0.f; clin = 0.f;
        #pragma unroll
        for (int i = 0; i < 56; ++i) {
            float2 v = s[i];
            clin += v.x;
            csq  += v.y;
            float n = n_other * (float)(i + 1);
            total += sqrtf(csq + 2.f * EPSF * clin + (EPSF * EPSF) * n) + EPSF;
        }
        sh[tid] = total;
    }
    __syncthreads();

    // ---- Phase C: reduce 64 partials ----
    if (tid < 32) {
        float v = sh[tid] + sh[tid + 32];
        #pragma unroll
        for (int off = 16; off > 0; off >>= 1)
            v += __shfl_down_sync(0xffffffffu, v, off);
        if (tid == 0) out[0] = v / 128.f;  // / (T=32 * 4 losses)
    }
}

// ---------------------------------------------------------------------------
extern "C" void kernel_launch(void* const* d_in, const int* in_sizes, int n_in,
                              void* d_out, int out_size)
{
    const float* x = (const float*)d_in[0];
    float* out = (float*)d_out;
    (void)in_sizes; (void)n_in; (void)out_size;

    dim3 grid(H_DIM, T_DIM);
    reduce_kernel<<<grid, 224>>>(x);
    finish_kernel<<<1, 1024>>>(out);
}

// round 6
// speedup vs baseline: 1.2907x; 1.2907x over previous
#include <cuda_runtime.h>

#define T_DIM 32
#define C_DIM 512
#define H_DIM 56
#define W_DIM 56
#define EPSF  1e-6f

// Packed (lin, sq) pairs.
// Per-(t,h) reductions for the H axis (block-exclusive -> plain store)
__device__ float2 g_H[T_DIM * H_DIM];
// Per-(t,h,w) partials for the W axis, folded over h by colreduce_kernel
__device__ float2 g_pW[T_DIM * H_DIM * W_DIM];
// Final W-axis reductions
__device__ float2 g_W[T_DIM * W_DIM];

// ---------------------------------------------------------------------------
// Kernel 1: stream the whole tensor once. Block = one (t, h) pair.
// 224 threads = 14 float4-quads (w) x 16 row slots (c).
// ---------------------------------------------------------------------------
__global__ __launch_bounds__(224) void reduce_kernel(const float* __restrict__ x)
{
    const int h   = blockIdx.x;
    const int t   = blockIdx.y;
    const int tid = threadIdx.x;
    const int q   = tid % 14;   // which float4 within the 56-wide row
    const int r0  = tid / 14;   // row (channel) slot 0..15

    // base points at element (t, c=0, h, w=0); h*56 is a multiple of 4 -> 16B aligned
    const float4* __restrict__ base =
        (const float4*)(x + ((size_t)t * C_DIM * H_DIM + (size_t)h) * W_DIM);
    const int stride4 = (H_DIM * W_DIM) / 4;  // 784 float4 per channel

    float linh = 0.f, sqh = 0.f;
    float lw0 = 0.f, lw1 = 0.f, lw2 = 0.f, lw3 = 0.f;
    float sw0 = 0.f, sw1 = 0.f, sw2 = 0.f, sw3 = 0.f;

    #pragma unroll 4
    for (int c = r0; c < C_DIM; c += 16) {
        float4 v = base[(size_t)c * stride4 + q];
        linh += v.x + v.y + v.z + v.w;
        sqh  += v.x * v.x + v.y * v.y + v.z * v.z + v.w * v.w;
        lw0 += v.x;  sw0 += v.x * v.x;
        lw1 += v.y;  sw1 += v.y * v.y;
        lw2 += v.z;  sw2 += v.z * v.z;
        lw3 += v.w;  sw3 += v.w * v.w;
    }

    __shared__ float sbuf[224 * 8];  // reused for both reductions

    // ---- H reduction: shfl within warp, then thread 0 folds the 7 warps ----
    float a = linh, b = sqh;
    #pragma unroll
    for (int off = 16; off > 0; off >>= 1) {
        a += __shfl_down_sync(0xffffffffu, a, off);
        b += __shfl_down_sync(0xffffffffu, b, off);
    }
    const int wid  = tid >> 5;
    const int lane = tid & 31;
    if (lane == 0) { sbuf[wid] = a; sbuf[8 + wid] = b; }
    __syncthreads();
    if (tid == 0) {
        float la = 0.f, lb = 0.f;
        #pragma unroll
        for (int i = 0; i < 7; ++i) { la += sbuf[i]; lb += sbuf[8 + i]; }
        g_H[t * H_DIM + h] = make_float2(la, lb);
    }
    __syncthreads();  // done with sbuf for H

    // ---- W partials: each thread parks its 8 values, 56 threads gather ----
    float* my = &sbuf[tid * 8];
    my[0] = lw0; my[1] = lw1; my[2] = lw2; my[3] = lw3;
    my[4] = sw0; my[5] = sw1; my[6] = sw2; my[7] = sw3;
    __syncthreads();

    if (tid < W_DIM) {
        const int qq = tid >> 2;   // quad owning this w
        const int ii = tid & 3;    // element within quad
        float la = 0.f, lb = 0.f;
        #pragma unroll
        for (int r = 0; r < 16; ++r) {
            const float* src = &sbuf[(r * 14 + qq) * 8];
            la += src[ii];
            lb += src[4 + ii];
        }
        g_pW[(t * H_DIM + h) * W_DIM + tid] = make_float2(la, lb);
    }
}

// ---------------------------------------------------------------------------
// Kernel 2: fold W partials over h. One block per t (32 blocks spread across
// SMs), thread per w; 56 fully-unrolled independent L2 loads -> latency hidden.
// ---------------------------------------------------------------------------
__global__ __launch_bounds__(64) void colreduce_kernel()
{
    const int t = blockIdx.x;
    const int w = threadIdx.x;
    if (w >= W_DIM) return;
    float a = 0.f, b = 0.f;
    #pragma unroll
    for (int hh = 0; hh < H_DIM; ++hh) {
        float2 v = g_pW[(t * H_DIM + hh) * W_DIM + w];
        a += v.x;
        b += v.y;
    }
    g_W[t * W_DIM + w] = make_float2(a, b);
}

// ---------------------------------------------------------------------------
// Kernel 3: cumsums + sqrt + mean. 64 threads = 32 t x 2 axes; reads 28 KB L2.
// ---------------------------------------------------------------------------
__global__ __launch_bounds__(64) void finish_kernel(float* __restrict__ out)
{
    const int tid = threadIdx.x;
    const int t   = tid & 31;
    const int ax  = tid >> 5;  // 0 = H, 1 = W

    const float2* __restrict__ s = (ax ? g_W : g_H) + t * 56;

    const float n_other = (float)(C_DIM) * 56.f;  // 28672
    float total = 0.f;

    // suffix slices [i:]
    float csq = 0.f, clin = 0.f;
    #pragma unroll
    for (int i = 55; i >= 0; --i) {
        float2 v = s[i];
        clin += v.x;
        csq  += v.y;
        float n = n_other * (float)(56 - i);
        total += sqrtf(csq + 2.f * EPSF * clin + (EPSF * EPSF) * n) + EPSF;
    }
    // prefix slices [:j+1]
    csq = 0.f; clin = 0.f;
    #pragma unroll
    for (int i = 0; i < 56; ++i) {
        float2 v = s[i];
        clin += v.x;
        csq  += v.y;
        float n = n_other * (float)(i + 1);
        total += sqrtf(csq + 2.f * EPSF * clin + (EPSF * EPSF) * n) + EPSF;
    }

    __shared__ float sh[64];
    sh[tid] = total;
    __syncthreads();
    if (tid < 32) {
        float v = sh[tid] + sh[tid + 32];
        #pragma unroll
        for (int off = 16; off > 0; off >>= 1)
            v += __shfl_down_sync(0xffffffffu, v, off);
        if (tid == 0) out[0] = v / 128.f;  // / (T=32 * 4 losses)
    }
}

// ---------------------------------------------------------------------------
extern "C" void kernel_launch(void* const* d_in, const int* in_sizes, int n_in,
                              void* d_out, int out_size)
{
    const float* x = (const float*)d_in[0];
    float* out = (float*)d_out;
    (void)in_sizes; (void)n_in; (void)out_size;

    dim3 grid(H_DIM, T_DIM);
    reduce_kernel<<<grid, 224>>>(x);
    colreduce_kernel<<<T_DIM, 64>>>();
    finish_kernel<<<1, 64>>>(out);
}

// round 7
// speedup vs baseline: 1.3784x; 1.0680x over previous
#include <cuda_runtime.h>

#define T_DIM 32
#define C_DIM 512
#define H_DIM 56
#define W_DIM 56
#define EPSF  1e-6f
#define NPAIR (T_DIM * H_DIM)   // 1792 (t,h) pairs
#define GRID1 (NPAIR / 2)       // 896 blocks, 2 pairs each -> one even wave

// Packed (lin, sq) pairs.
__device__ float2 g_H[T_DIM * H_DIM];                 // H-axis finals
__device__ float2 g_pW[T_DIM * H_DIM * W_DIM];        // W-axis partials (per t,h)
__device__ float2 g_W[T_DIM * W_DIM];                 // W-axis finals
__device__ unsigned int g_ticket;                     // zero-init; last block resets

// ---------------------------------------------------------------------------
// Kernel 1: stream the whole tensor once. 896 blocks x 224 threads; each block
// handles 2 (t,h) pairs so the grid is exactly one balanced wave (~6 blk/SM).
// 224 threads = 14 float4-quads (w) x 16 row slots (c).
// ---------------------------------------------------------------------------
__global__ __launch_bounds__(224) void reduce_kernel(const float* __restrict__ x)
{
    const int tid = threadIdx.x;
    const int q   = tid % 14;   // which float4 within the 56-wide row
    const int r0  = tid / 14;   // row (channel) slot 0..15
    const int wid  = tid >> 5;
    const int lane = tid & 31;
    const int stride4 = (H_DIM * W_DIM) / 4;  // 784 float4 per channel

    __shared__ float sbuf[224 * 8];

    #pragma unroll
    for (int pp = 0; pp < 2; ++pp) {
        const int p = blockIdx.x + pp * GRID1;
        const int t = p / H_DIM;
        const int h = p % H_DIM;

        const float4* __restrict__ base =
            (const float4*)(x + ((size_t)t * C_DIM * H_DIM + (size_t)h) * W_DIM);

        float linh = 0.f, sqh = 0.f;
        float lw0 = 0.f, lw1 = 0.f, lw2 = 0.f, lw3 = 0.f;
        float sw0 = 0.f, sw1 = 0.f, sw2 = 0.f, sw3 = 0.f;

        #pragma unroll 4
        for (int c = r0; c < C_DIM; c += 16) {
            float4 v = base[(size_t)c * stride4 + q];
            linh += v.x + v.y + v.z + v.w;
            sqh  += v.x * v.x + v.y * v.y + v.z * v.z + v.w * v.w;
            lw0 += v.x;  sw0 += v.x * v.x;
            lw1 += v.y;  sw1 += v.y * v.y;
            lw2 += v.z;  sw2 += v.z * v.z;
            lw3 += v.w;  sw3 += v.w * v.w;
        }

        // ---- H reduction: shfl within warp, thread 0 folds the 7 warps ----
        float a = linh, b = sqh;
        #pragma unroll
        for (int off = 16; off > 0; off >>= 1) {
            a += __shfl_down_sync(0xffffffffu, a, off);
            b += __shfl_down_sync(0xffffffffu, b, off);
        }
        if (lane == 0) { sbuf[wid] = a; sbuf[8 + wid] = b; }
        __syncthreads();
        if (tid == 0) {
            float la = 0.f, lb = 0.f;
            #pragma unroll
            for (int i = 0; i < 7; ++i) { la += sbuf[i]; lb += sbuf[8 + i]; }
            g_H[t * H_DIM + h] = make_float2(la, lb);
        }
        __syncthreads();  // done with sbuf for H

        // ---- W partials: each thread parks its 8 values, 56 threads gather ----
        float* my = &sbuf[tid * 8];
        my[0] = lw0; my[1] = lw1; my[2] = lw2; my[3] = lw3;
        my[4] = sw0; my[5] = sw1; my[6] = sw2; my[7] = sw3;
        __syncthreads();

        if (tid < W_DIM) {
            const int qq = tid >> 2;   // quad owning this w
            const int ii = tid & 3;    // element within quad
            float la = 0.f, lb = 0.f;
            #pragma unroll
            for (int r = 0; r < 16; ++r) {
                const float* src = &sbuf[(r * 14 + qq) * 8];
                la += src[ii];
                lb += src[4 + ii];
            }
            g_pW[(t * H_DIM + h) * W_DIM + tid] = make_float2(la, lb);
        }
        __syncthreads();  // sbuf reused by next pair
    }
}

// ---------------------------------------------------------------------------
// Kernel 2 (fused): fold W partials over h (one block per t, 32 blocks), then
// the LAST block to finish performs the cumsum/sqrt/mean epilogue.
// Ticket pattern: __threadfence + atomicAdd; last block resets the counter so
// every graph replay starts from 0 (deterministic).
// ---------------------------------------------------------------------------
__global__ __launch_bounds__(64) void colreduce_finish_kernel(float* __restrict__ out)
{
    const int t0  = blockIdx.x;
    const int tid = threadIdx.x;

    // ---- column reduce for this block's t ----
    if (tid < W_DIM) {
        float a = 0.f, b = 0.f;
        #pragma unroll
        for (int hh = 0; hh < H_DIM; ++hh) {
            float2 v = g_pW[(t0 * H_DIM + hh) * W_DIM + tid];
            a += v.x;
            b += v.y;
        }
        g_W[t0 * W_DIM + tid] = make_float2(a, b);
    }
    __threadfence();
    __syncthreads();

    // ---- elect last block ----
    __shared__ unsigned int s_last;
    if (tid == 0) s_last = atomicAdd(&g_ticket, 1u);
    __syncthreads();
    if (s_last != T_DIM - 1) return;
    if (tid == 0) g_ticket = 0;   // reset for next launch/replay
    __threadfence();

    // ---- finish: scans over the 56-length final arrays ----
    const int t  = tid & 31;
    const int ax = tid >> 5;  // 0 = H, 1 = W
    const float2* __restrict__ s = (ax ? g_W : g_H) + t * 56;

    const float n_other = (float)(C_DIM) * 56.f;  // 28672
    float total = 0.f;

    float csq = 0.f, clin = 0.f;
    #pragma unroll
    for (int i = 55; i >= 0; --i) {           // suffix slices [i:]
        float2 v = s[i];
        clin += v.x;
        csq  += v.y;
        float n = n_other * (float)(56 - i);
        total += sqrtf(csq + 2.f * EPSF * clin + (EPSF * EPSF) * n) + EPSF;
    }
    csq = 0.f; clin = 0.f;
    #pragma unroll
    for (int i = 0; i < 56; ++i) {            // prefix slices [:j+1]
        float2 v = s[i];
        clin += v.x;
        csq  += v.y;
        float n = n_other * (float)(i + 1);
        total += sqrtf(csq + 2.f * EPSF * clin + (EPSF * EPSF) * n) + EPSF;
    }

    __shared__ float sh[64];
    sh[tid] = total;
    __syncthreads();
    if (tid < 32) {
        float v = sh[tid] + sh[tid + 32];
        #pragma unroll
        for (int off = 16; off > 0; off >>= 1)
            v += __shfl_down_sync(0xffffffffu, v, off);
        if (tid == 0) out[0] = v / 128.f;  // / (T=32 * 4 losses)
    }
}

// ---------------------------------------------------------------------------
extern "C" void kernel_launch(void* const* d_in, const int* in_sizes, int n_in,
                              void* d_out, int out_size)
{
    const float* x = (const float*)d_in[0];
    float* out = (float*)d_out;
    (void)in_sizes; (void)n_in; (void)out_size;

    reduce_kernel<<<GRID1, 224>>>(x);
    colreduce_finish_kernel<<<T_DIM, 64>>>(out);
}

// round 8
// speedup vs baseline: 1.3847x; 1.0045x over previous
#include <cuda_runtime.h>

#define T_DIM 32
#define C_DIM 512
#define H_DIM 56
#define W_DIM 56
#define EPSF  1e-6f
#define NPAIR (T_DIM * H_DIM)   // 1792 (t,h) pairs
#define GRID1 (NPAIR / 2)       // 896 blocks, 2 pairs each -> one even wave
#define HG    7                 // h-groups of 8 in the tail kernel
#define GRID2 (T_DIM * HG)      // 224 tail blocks

// Packed (lin, sq) pairs.
__device__ float2 g_H[T_DIM * H_DIM];                 // H-axis finals
__device__ float2 g_pW[T_DIM * H_DIM * W_DIM];        // W-axis partials (per t,h)
__device__ float2 g_W1[T_DIM * HG * W_DIM];           // W partials folded over 8 h
__device__ unsigned int g_ticket;                     // zero-init; last block resets

// ---------------------------------------------------------------------------
// Kernel 1: stream the whole tensor once. 896 blocks x 224 threads; each block
// handles 2 (t,h) pairs (one balanced wave). Streaming loads use __ldcs
// (evict-first) so the 205MB stream does not evict the partials from L2.
// 224 threads = 14 float4-quads (w) x 16 row slots (c).
// ---------------------------------------------------------------------------
__global__ __launch_bounds__(224) void reduce_kernel(const float* __restrict__ x)
{
    const int tid = threadIdx.x;
    const int q   = tid % 14;   // which float4 within the 56-wide row
    const int r0  = tid / 14;   // row (channel) slot 0..15
    const int wid  = tid >> 5;
    const int lane = tid & 31;
    const int stride4 = (H_DIM * W_DIM) / 4;  // 784 float4 per channel

    __shared__ float sbuf[224 * 8];

    #pragma unroll
    for (int pp = 0; pp < 2; ++pp) {
        const int p = blockIdx.x + pp * GRID1;
        const int t = p / H_DIM;
        const int h = p % H_DIM;

        const float4* __restrict__ base =
            (const float4*)(x + ((size_t)t * C_DIM * H_DIM + (size_t)h) * W_DIM);

        float linh = 0.f, sqh = 0.f;
        float lw0 = 0.f, lw1 = 0.f, lw2 = 0.f, lw3 = 0.f;
        float sw0 = 0.f, sw1 = 0.f, sw2 = 0.f, sw3 = 0.f;

        #pragma unroll 4
        for (int c = r0; c < C_DIM; c += 16) {
            float4 v = __ldcs(&base[(size_t)c * stride4 + q]);
            linh += v.x + v.y + v.z + v.w;
            sqh  += v.x * v.x + v.y * v.y + v.z * v.z + v.w * v.w;
            lw0 += v.x;  sw0 += v.x * v.x;
            lw1 += v.y;  sw1 += v.y * v.y;
            lw2 += v.z;  sw2 += v.z * v.z;
            lw3 += v.w;  sw3 += v.w * v.w;
        }

        // ---- H reduction: shfl within warp, thread 0 folds the 7 warps ----
        float a = linh, b = sqh;
        #pragma unroll
        for (int off = 16; off > 0; off >>= 1) {
            a += __shfl_down_sync(0xffffffffu, a, off);
            b += __shfl_down_sync(0xffffffffu, b, off);
        }
        if (lane == 0) { sbuf[wid] = a; sbuf[8 + wid] = b; }
        __syncthreads();
        if (tid == 0) {
            float la = 0.f, lb = 0.f;
            #pragma unroll
            for (int i = 0; i < 7; ++i) { la += sbuf[i]; lb += sbuf[8 + i]; }
            g_H[t * H_DIM + h] = make_float2(la, lb);
        }
        __syncthreads();  // done with sbuf for H

        // ---- W partials: each thread parks its 8 values, 56 threads gather ----
        float* my = &sbuf[tid * 8];
        my[0] = lw0; my[1] = lw1; my[2] = lw2; my[3] = lw3;
        my[4] = sw0; my[5] = sw1; my[6] = sw2; my[7] = sw3;
        __syncthreads();

        if (tid < W_DIM) {
            const int qq = tid >> 2;   // quad owning this w
            const int ii = tid & 3;    // element within quad
            float la = 0.f, lb = 0.f;
            #pragma unroll
            for (int r = 0; r < 16; ++r) {
                const float* src = &sbuf[(r * 14 + qq) * 8];
                la += src[ii];
                lb += src[4 + ii];
            }
            g_pW[(t * H_DIM + h) * W_DIM + tid] = make_float2(la, lb);
        }
        __syncthreads();  // sbuf reused by next pair
    }
}

// ---------------------------------------------------------------------------
// Kernel 2: 224 blocks x 64 threads. Block (t, hg) folds 8 h-partials into
// g_W1. The LAST block (ticket election; counter reset -> deterministic across
// graph replays) stages the 7-way fold + g_H into shared and runs the scans.
// ---------------------------------------------------------------------------
__global__ __launch_bounds__(64) void colreduce_finish_kernel(float* __restrict__ out)
{
    const int blk = blockIdx.x;
    const int tid = threadIdx.x;
    const int t0  = blk / HG;
    const int hg  = blk % HG;

    // ---- fold 8 h values for this (t, hg) ----
    if (tid < W_DIM) {
        float a = 0.f, b = 0.f;
        #pragma unroll
        for (int k = 0; k < 8; ++k) {
            float2 v = g_pW[(t0 * H_DIM + hg * 8 + k) * W_DIM + tid];
            a += v.x;
            b += v.y;
        }
        g_W1[(t0 * HG + hg) * W_DIM + tid] = make_float2(a, b);
    }
    __threadfence();
    __syncthreads();

    // ---- elect last block ----
    __shared__ unsigned int s_last;
    if (tid == 0) s_last = atomicAdd(&g_ticket, 1u);
    __syncthreads();
    if (s_last != GRID2 - 1) return;
    if (tid == 0) g_ticket = 0;   // reset for next launch/replay
    __threadfence();

    // ---- stage finals into shared: W via 7-way fold of g_W1, H direct ----
    __shared__ float2 sh_W[T_DIM * W_DIM];
    __shared__ float2 sh_H[T_DIM * H_DIM];
    for (int p = tid; p < T_DIM * W_DIM; p += 64) {
        const int t = p / W_DIM;
        const int w = p % W_DIM;
        float a = 0.f, b = 0.f;
        #pragma unroll
        for (int g = 0; g < HG; ++g) {
            float2 v = g_W1[(t * HG + g) * W_DIM + w];
            a += v.x;
            b += v.y;
        }
        sh_W[p] = make_float2(a, b);
        sh_H[p] = g_H[p];
    }
    __syncthreads();

    // ---- scans: 64 threads = 32 t x 2 axes ----
    const int t  = tid & 31;
    const int ax = tid >> 5;  // 0 = H, 1 = W
    const float2* __restrict__ s = (ax ? sh_W : sh_H) + t * 56;

    const float n_other = (float)(C_DIM) * 56.f;  // 28672
    float total = 0.f;

    float csq = 0.f, clin = 0.f;
    #pragma unroll
    for (int i = 55; i >= 0; --i) {           // suffix slices [i:]
        float2 v = s[i];
        clin += v.x;
        csq  += v.y;
        float n = n_other * (float)(56 - i);
        total += sqrtf(csq + 2.f * EPSF * clin + (EPSF * EPSF) * n) + EPSF;
    }
    csq = 0.f; clin = 0.f;
    #pragma unroll
    for (int i = 0; i < 56; ++i) {            // prefix slices [:j+1]
        float2 v = s[i];
        clin += v.x;
        csq  += v.y;
        float n = n_other * (float)(i + 1);
        total += sqrtf(csq + 2.f * EPSF * clin + (EPSF * EPSF) * n) + EPSF;
    }

    __shared__ float sh[64];
    sh[tid] = total;
    __syncthreads();
    if (tid < 32) {
        float v = sh[tid] + sh[tid + 32];
        #pragma unroll
        for (int off = 16; off > 0; off >>= 1)
            v += __shfl_down_sync(0xffffffffu, v, off);
        if (tid == 0) out[0] = v / 128.f;  // / (T=32 * 4 losses)
    }
}

// ---------------------------------------------------------------------------
extern "C" void kernel_launch(void* const* d_in, const int* in_sizes, int n_in,
                              void* d_out, int out_size)
{
    const float* x = (const float*)d_in[0];
    float* out = (float*)d_out;
    (void)in_sizes; (void)n_in; (void)out_size;

    reduce_kernel<<<GRID1, 224>>>(x);
    colreduce_finish_kernel<<<GRID2, 64>>>(out);
}